// round 7
// baseline (speedup 1.0000x reference)
#include <cuda_runtime.h>

// Problem constants
#define BB 4
#define TT 512
#define NF 513
#define NK 128
#define NROWS (BB*TT)            // 2048
#define ROWS 8
#define NBLOCKS (NROWS/ROWS)     // 256
#define THREADS 256
#define FTILE 64
#define FBT_STRIDE 65            // [k][fl] stride; odd => conflict-free both phases
#define SPEC_STRIDE 516          // padded global row stride (words); rows 16B-aligned
#define MAX_ITER_C 30
#define LR_C 0.1f
#define MOM_C 0.9f
#define INV_N_C (1.0f/2048.0f)
#define TOL_LOSS_C 1e-5f
#define TOL_CHANGE_C 1e-8f

// Scratch state (device globals — no allocation allowed). Padded row stride.
__device__ __align__(16) float g_spec[NROWS * SPEC_STRIDE];
__device__ __align__(16) float g_buf[NROWS * SPEC_STRIDE];
__device__ float g_rowloss[NROWS];
__device__ float g_prev_loss;
__device__ int   g_done;

// ---------------------------------------------------------------------------
__global__ void init_kernel(const float* __restrict__ spec_init) {
    int i = blockIdx.x * blockDim.x + threadIdx.x;
    if (i < NROWS * NF) {
        int r = i / NF;
        int f = i - r * NF;
        g_spec[r * SPEC_STRIDE + f] = spec_init[i];
        g_buf[r * SPEC_STRIDE + f]  = 0.0f;
    }
    if (i == 0) {
        g_prev_loss = __int_as_float(0x7f800000);  // +inf
        g_done = 0;
    }
}

// ---------------------------------------------------------------------------
// Fused per-iteration kernel. Each block owns ROWS=8 consecutive rows (b,t).
//   Phase 1: diff[r][k] = m[r][k] - sum_f spec[r][f]*fb[f][k]   (diff in smem)
//            per-row sum of diff^2 -> g_rowloss
//   Phase 2: grad[r][f] = -2/N * sum_k diff[r][k]*fb[f][k]
//            buf = MOM*buf + grad ; spec = max(spec - LR*buf, 0)
//            (gated on g_done, which reflects losses of PREVIOUS iterations)
// fb tile cached transposed in smem [k][fl] stride 65: conflict-free whether
// lanes vary k (phase 1) or fl (phase 2). spec lives in padded global memory
// (L1-resident per block) and is read via broadcast LDG.128.
__global__ __launch_bounds__(THREADS) void iter_kernel(
        const float* __restrict__ barkspec,   // (B, K, T)
        const float* __restrict__ fb) {       // (NF, NK)
    __shared__ float s_fbT[NK * FBT_STRIDE];              // 33280 B
    __shared__ __align__(16) float s_diff[ROWS * NK];     // 4096 B, rows 512B-aligned

    const int tid  = threadIdx.x;
    const int row0 = blockIdx.x * ROWS;

    // ---- Phase 1: diff ----
    const int k  = tid & (NK - 1);
    const int rb = (tid >> 7) << 2;   // 0 or 4 : this thread handles rows rb..rb+3
    float4 acc;
    {
        // m[r][k] = barkspec[b][k][t]; rows rb..rb+3 are consecutive t in one b
        int r0 = row0 + rb;
        int b  = r0 >> 9;        // /512
        int t  = r0 & (TT - 1);  // multiple of 4 -> float4 aligned
        acc = *reinterpret_cast<const float4*>(
            barkspec + ((size_t)(b * NK + k)) * TT + t);
    }
    const float* __restrict__ sr0 = g_spec + (size_t)(row0 + rb + 0) * SPEC_STRIDE;
    const float* __restrict__ sr1 = g_spec + (size_t)(row0 + rb + 1) * SPEC_STRIDE;
    const float* __restrict__ sr2 = g_spec + (size_t)(row0 + rb + 2) * SPEC_STRIDE;
    const float* __restrict__ sr3 = g_spec + (size_t)(row0 + rb + 3) * SPEC_STRIDE;

    for (int ft = 0; ft < NF; ft += FTILE) {
        int fcnt = min(FTILE, NF - ft);
        __syncthreads();   // prior tile consumers done
        for (int i = tid; i < fcnt * NK; i += THREADS) {
            int fl = i >> 7;
            int k2 = i & (NK - 1);
            s_fbT[k2 * FBT_STRIDE + fl] = fb[(ft + fl) * NK + k2];
        }
        __syncthreads();
        const float* wp = s_fbT + k * FBT_STRIDE;
        if (fcnt == FTILE) {
            #pragma unroll
            for (int fl = 0; fl < FTILE; fl += 4) {
                float4 a0 = *reinterpret_cast<const float4*>(sr0 + ft + fl);
                float4 a1 = *reinterpret_cast<const float4*>(sr1 + ft + fl);
                float4 a2 = *reinterpret_cast<const float4*>(sr2 + ft + fl);
                float4 a3 = *reinterpret_cast<const float4*>(sr3 + ft + fl);
                float w0 = wp[fl + 0];
                float w1 = wp[fl + 1];
                float w2 = wp[fl + 2];
                float w3 = wp[fl + 3];
                acc.x = fmaf(-a0.x, w0, acc.x);
                acc.y = fmaf(-a1.x, w0, acc.y);
                acc.z = fmaf(-a2.x, w0, acc.z);
                acc.w = fmaf(-a3.x, w0, acc.w);
                acc.x = fmaf(-a0.y, w1, acc.x);
                acc.y = fmaf(-a1.y, w1, acc.y);
                acc.z = fmaf(-a2.y, w1, acc.z);
                acc.w = fmaf(-a3.y, w1, acc.w);
                acc.x = fmaf(-a0.z, w2, acc.x);
                acc.y = fmaf(-a1.z, w2, acc.y);
                acc.z = fmaf(-a2.z, w2, acc.z);
                acc.w = fmaf(-a3.z, w2, acc.w);
                acc.x = fmaf(-a0.w, w3, acc.x);
                acc.y = fmaf(-a1.w, w3, acc.y);
                acc.z = fmaf(-a2.w, w3, acc.z);
                acc.w = fmaf(-a3.w, w3, acc.w);
            }
        } else {
            for (int fl = 0; fl < fcnt; fl++) {
                float w = wp[fl];
                acc.x = fmaf(-sr0[ft + fl], w, acc.x);
                acc.y = fmaf(-sr1[ft + fl], w, acc.y);
                acc.z = fmaf(-sr2[ft + fl], w, acc.z);
                acc.w = fmaf(-sr3[ft + fl], w, acc.w);
            }
        }
    }
    s_diff[(rb + 0) * NK + k] = acc.x;
    s_diff[(rb + 1) * NK + k] = acc.y;
    s_diff[(rb + 2) * NK + k] = acc.z;
    s_diff[(rb + 3) * NK + k] = acc.w;
    __syncthreads();

    // Per-row loss: warp w reduces row w (fixed order -> deterministic)
    {
        int warp = tid >> 5, lane = tid & 31;
        float s = 0.0f;
        #pragma unroll
        for (int j = 0; j < NK / 32; j++) {
            float d = s_diff[warp * NK + lane + j * 32];
            s = fmaf(d, d, s);
        }
        #pragma unroll
        for (int off = 16; off; off >>= 1)
            s += __shfl_xor_sync(0xffffffffu, s, off);
        if (lane == 0) g_rowloss[row0 + warp] = s;
    }

    const int done = g_done;   // set by reduce_kernel of the PREVIOUS iteration

    // ---- Phase 2: grad + SGD update (2 rows per thread) ----
    const int lane = tid & 31;
    const int wrp  = tid >> 5;        // 0..7
    const int pr   = wrp & 3;         // row pair 0..3
    const int half = wrp >> 2;        // f-half 0..1
    const int r2a  = 2 * pr;
    const int r2b  = 2 * pr + 1;
    const float* dA = s_diff + r2a * NK;   // 512B-aligned
    const float* dB = s_diff + r2b * NK;
    for (int ft = 0; ft < NF; ft += FTILE) {
        int fcnt = min(FTILE, NF - ft);
        __syncthreads();
        for (int i = tid; i < fcnt * NK; i += THREADS) {
            int fl = i >> 7;
            int k2 = i & (NK - 1);
            s_fbT[k2 * FBT_STRIDE + fl] = fb[(ft + fl) * NK + k2];
        }
        __syncthreads();
        int flo = half * 32 + lane;
        if (flo < fcnt) {
            float a0 = 0.0f, a1 = 0.0f;
            #pragma unroll 8
            for (int kk = 0; kk < NK; kk += 4) {
                float4 da = *reinterpret_cast<const float4*>(dA + kk);
                float4 db = *reinterpret_cast<const float4*>(dB + kk);
                float w0 = s_fbT[(kk + 0) * FBT_STRIDE + flo];
                float w1 = s_fbT[(kk + 1) * FBT_STRIDE + flo];
                float w2 = s_fbT[(kk + 2) * FBT_STRIDE + flo];
                float w3 = s_fbT[(kk + 3) * FBT_STRIDE + flo];
                a0 = fmaf(da.x, w0, a0);
                a1 = fmaf(db.x, w0, a1);
                a0 = fmaf(da.y, w1, a0);
                a1 = fmaf(db.y, w1, a1);
                a0 = fmaf(da.z, w2, a0);
                a1 = fmaf(db.z, w2, a1);
                a0 = fmaf(da.w, w3, a0);
                a1 = fmaf(db.w, w3, a1);
            }
            if (!done) {
                int f = ft + flo;
                size_t ia = (size_t)(row0 + r2a) * SPEC_STRIDE + f;
                size_t ib = (size_t)(row0 + r2b) * SPEC_STRIDE + f;
                float ga = (-2.0f * INV_N_C) * a0;
                float gb = (-2.0f * INV_N_C) * a1;
                float bna = fmaf(MOM_C, g_buf[ia], ga);
                float bnb = fmaf(MOM_C, g_buf[ib], gb);
                g_buf[ia] = bna;
                g_buf[ib] = bnb;
                g_spec[ia] = fmaxf(fmaf(-LR_C, bna, g_spec[ia]), 0.0f);
                g_spec[ib] = fmaxf(fmaf(-LR_C, bnb, g_spec[ib]), 0.0f);
            }
        }
    }
}

// ---------------------------------------------------------------------------
// Deterministic loss reduction + stop-flag latch (runs AFTER the update kernel
// of the same iteration, matching the reference's done-gating order).
__global__ void reduce_kernel() {
    __shared__ float warp_s[8];
    int tid = threadIdx.x;   // 256 threads
    float s = 0.0f;
    #pragma unroll
    for (int j = 0; j < NROWS / 256; j++) s += g_rowloss[tid + j * 256];
    #pragma unroll
    for (int off = 16; off; off >>= 1) s += __shfl_xor_sync(0xffffffffu, s, off);
    if ((tid & 31) == 0) warp_s[tid >> 5] = s;
    __syncthreads();
    if (tid == 0) {
        float tot = 0.0f;
        #pragma unroll
        for (int w = 0; w < 8; w++) tot += warp_s[w];
        float loss = tot * INV_N_C;
        if (!g_done) {
            float prev = g_prev_loss;
            int stop = (loss < TOL_LOSS_C) || (fabsf(prev - loss) < TOL_CHANGE_C);
            g_prev_loss = loss;
            if (stop) g_done = 1;
        }
    }
}

// ---------------------------------------------------------------------------
// out[b][f][t] = g_spec[(b*T + t)*SPEC_STRIDE + f]
__global__ void transpose_kernel(float* __restrict__ out) {
    __shared__ float tile[32][33];
    int b  = blockIdx.z;
    int f0 = blockIdx.x * 32;
    int t0 = blockIdx.y * 32;
    int tx = threadIdx.x, ty = threadIdx.y;   // 32 x 8
    for (int i = ty; i < 32; i += 8) {
        int f = f0 + tx, t = t0 + i;
        tile[i][tx] = (f < NF)
            ? g_spec[((size_t)(b * TT + t)) * SPEC_STRIDE + f] : 0.0f;
    }
    __syncthreads();
    for (int i = ty; i < 32; i += 8) {
        int f = f0 + i, t = t0 + tx;
        if (f < NF) out[((size_t)b * NF + f) * TT + t] = tile[tx][i];
    }
}

// ---------------------------------------------------------------------------
extern "C" void kernel_launch(void* const* d_in, const int* in_sizes, int n_in,
                              void* d_out, int out_size) {
    // Identify inputs by element count (robust to ordering)
    const float* barkspec  = nullptr;   // 4*128*512   = 262144
    const float* fb        = nullptr;   // 513*128     = 65664
    const float* spec_init = nullptr;   // 4*512*513   = 1050624
    for (int i = 0; i < n_in; i++) {
        if (in_sizes[i] == BB * NK * TT)      barkspec  = (const float*)d_in[i];
        else if (in_sizes[i] == NF * NK)      fb        = (const float*)d_in[i];
        else if (in_sizes[i] == NROWS * NF)   spec_init = (const float*)d_in[i];
    }
    float* out = (float*)d_out;

    init_kernel<<<(NROWS * NF + 255) / 256, 256>>>(spec_init);
    for (int it = 0; it < MAX_ITER_C; it++) {
        iter_kernel<<<NBLOCKS, THREADS>>>(barkspec, fb);
        reduce_kernel<<<1, 256>>>();
    }
    dim3 tgrid((NF + 31) / 32, TT / 32, BB);
    transpose_kernel<<<tgrid, dim3(32, 8)>>>(out);
}

// round 11
// speedup vs baseline: 1.1474x; 1.1474x over previous
#include <cuda_runtime.h>

// Problem constants
#define BB 4
#define TT 512
#define NF 513
#define NK 128
#define NROWS (BB*TT)            // 2048
#define ROWS 8
#define NBLOCKS (NROWS/ROWS)     // 256
#define THREADS 512
#define FTILE 32
#define NTILES 17                // 16*32 + 1
#define FBT_STRIDE 33            // [k][fl] stride; conflict-free both phases
#define SPEC_STRIDE 516          // padded global row stride (words); rows 16B-aligned
#define MAX_ITER_C 30
#define LR_C 0.1f
#define MOM_C 0.9f
#define INV_N_C (1.0f/2048.0f)
#define TOL_LOSS_C 1e-5f
#define TOL_CHANGE_C 1e-8f

// Scratch state (device globals — no allocation allowed). Padded row stride.
__device__ __align__(16) float g_spec[NROWS * SPEC_STRIDE];
__device__ __align__(16) float g_buf[NROWS * SPEC_STRIDE];
__device__ float g_rowloss[NROWS];
__device__ float g_prev_loss;
__device__ int   g_done;
__device__ int   g_ticket;

// ---------------------------------------------------------------------------
__global__ void init_kernel(const float* __restrict__ spec_init) {
    int i = blockIdx.x * blockDim.x + threadIdx.x;
    if (i < NROWS * NF) {
        int r = i / NF;
        int f = i - r * NF;
        g_spec[r * SPEC_STRIDE + f] = spec_init[i];
        g_buf[r * SPEC_STRIDE + f]  = 0.0f;
    }
    if (i == 0) {
        g_prev_loss = __int_as_float(0x7f800000);  // +inf
        g_done = 0;
        g_ticket = 0;
    }
}

// ---------------------------------------------------------------------------
// Fused per-iteration kernel. Each block owns ROWS=8 consecutive rows (b,t).
//   Phase 1: diff[r][k] = m[r][k] - sum_f spec[r][f]*fb[f][k]   (diff in smem)
//            per-row sum(diff^2) -> g_rowloss
//   Phase 2: grad[r][f] = -2/N * sum_k diff[r][k]*fb[f][k]
//            buf = MOM*buf + grad ; spec = max(spec - LR*buf, 0)
//            (gated on g_done = losses of PREVIOUS iterations)
//   Tail  : last block (atomic ticket) reduces g_rowloss, latches done/prev.
// fb tiles are software-pipelined through double-buffered smem (one sync per
// tile, LDG prefetch overlapped with compute). fbT layout [k][fl] stride 33 is
// bank-conflict-free for both k-varying (ph1) and fl-varying (ph2) lanes.
__global__ __launch_bounds__(THREADS) void iter_kernel(
        const float* __restrict__ barkspec,   // (B, K, T)
        const float* __restrict__ fb) {       // (NF, NK)
    __shared__ float s_fbT[2][NK * FBT_STRIDE];           // 2 x 16.9KB
    __shared__ __align__(16) float s_diff[ROWS * NK];     // 4KB
    __shared__ float s_part[2][ROWS][32];                 // 2KB
    __shared__ float s_warp[8];
    __shared__ int   s_last;

    const int tid  = threadIdx.x;
    const int row0 = blockIdx.x * ROWS;
    const int lane = tid & 31;
    const int wrp  = tid >> 5;          // 0..15

    // ---- Phase 1: diff (thread = (k, row-pair)) ----
    const int k  = tid & (NK - 1);
    const int rg = tid >> 7;            // 0..3
    const int r2 = rg * 2;
    float2 acc;
    {
        int r0g = row0 + r2;
        int b = r0g >> 9, t = r0g & (TT - 1);   // t even -> float2 aligned
        acc = *reinterpret_cast<const float2*>(
            barkspec + ((size_t)(b * NK + k)) * TT + t);
    }
    const float* sA = g_spec + (size_t)(row0 + r2) * SPEC_STRIDE;
    const float* sB = sA + SPEC_STRIDE;

    // prologue: tile 0 -> buf 0
    #pragma unroll
    for (int j = 0; j < 8; j++) {
        int i = tid + j * THREADS;
        int fl = i >> 7, k2 = i & (NK - 1);
        s_fbT[0][k2 * FBT_STRIDE + fl] = fb[fl * NK + k2];
    }
    __syncthreads();

    int p = 0;
    #pragma unroll 1
    for (int tile = 0; tile < NTILES; tile++) {
        const int ft = tile * FTILE;
        const bool hp = (tile < NTILES - 1);
        const int nft = ft + FTILE;
        const int nfcnt = (tile == NTILES - 2) ? (NF - nft) : FTILE;
        float pre[8];
        if (hp) {
            #pragma unroll
            for (int j = 0; j < 8; j++) {
                int i = tid + j * THREADS;
                int fl = i >> 7, k2 = i & (NK - 1);
                pre[j] = (fl < nfcnt) ? fb[(nft + fl) * NK + k2] : 0.0f;
            }
        }
        const float* wp = s_fbT[p] + k * FBT_STRIDE;
        if (tile < NTILES - 1) {
            #pragma unroll
            for (int fl = 0; fl < FTILE; fl += 4) {
                float4 a0 = *reinterpret_cast<const float4*>(sA + ft + fl);
                float4 a1 = *reinterpret_cast<const float4*>(sB + ft + fl);
                float w0 = wp[fl + 0], w1 = wp[fl + 1];
                float w2 = wp[fl + 2], w3 = wp[fl + 3];
                acc.x = fmaf(-a0.x, w0, acc.x);  acc.y = fmaf(-a1.x, w0, acc.y);
                acc.x = fmaf(-a0.y, w1, acc.x);  acc.y = fmaf(-a1.y, w1, acc.y);
                acc.x = fmaf(-a0.z, w2, acc.x);  acc.y = fmaf(-a1.z, w2, acc.y);
                acc.x = fmaf(-a0.w, w3, acc.x);  acc.y = fmaf(-a1.w, w3, acc.y);
            }
        } else {  // tail tile: single f = 512
            float w0 = wp[0];
            acc.x = fmaf(-sA[NF - 1], w0, acc.x);
            acc.y = fmaf(-sB[NF - 1], w0, acc.y);
        }
        if (hp) {
            #pragma unroll
            for (int j = 0; j < 8; j++) {
                int i = tid + j * THREADS;
                int fl = i >> 7, k2 = i & (NK - 1);
                if (fl < nfcnt) s_fbT[1 - p][k2 * FBT_STRIDE + fl] = pre[j];
            }
        }
        __syncthreads();
        p ^= 1;
    }

    s_diff[(r2 + 0) * NK + k] = acc.x;
    s_diff[(r2 + 1) * NK + k] = acc.y;
    __syncthreads();

    // Per-row loss: warp w (0..7) reduces row w (fixed order -> deterministic)
    if (wrp < ROWS) {
        float s = 0.0f;
        #pragma unroll
        for (int j = 0; j < NK / 32; j++) {
            float d = s_diff[wrp * NK + lane + j * 32];
            s = fmaf(d, d, s);
        }
        #pragma unroll
        for (int off = 16; off; off >>= 1)
            s += __shfl_xor_sync(0xffffffffu, s, off);
        if (lane == 0) g_rowloss[row0 + wrp] = s;
    }

    const int done = g_done;   // latched by last block of the PREVIOUS iteration

    // ---- Phase 2: grad + SGD update (warp = (row, k-half), lane = f) ----
    // prologue: tile 0 -> buf 0 (s_fbT free after phase-1 final sync)
    #pragma unroll
    for (int j = 0; j < 8; j++) {
        int i = tid + j * THREADS;
        int fl = i >> 7, k2 = i & (NK - 1);
        s_fbT[0][k2 * FBT_STRIDE + fl] = fb[fl * NK + k2];
    }
    __syncthreads();

    const int r = wrp >> 1;          // 0..7
    const int h = wrp & 1;           // k-half
    const float* dr = s_diff + r * NK + h * 64;   // 16B-aligned
    int pb = 0;
    #pragma unroll 1
    for (int tile = 0; tile < NTILES; tile++) {
        const int ft = tile * FTILE;
        const int fcnt = (tile == NTILES - 1) ? (NF - ft) : FTILE;
        const bool hp = (tile < NTILES - 1);
        const int nft = ft + FTILE;
        const int nfcnt = (tile == NTILES - 2) ? (NF - nft) : FTILE;
        float pre[8];
        if (hp) {
            #pragma unroll
            for (int j = 0; j < 8; j++) {
                int i = tid + j * THREADS;
                int fl = i >> 7, k2 = i & (NK - 1);
                pre[j] = (fl < nfcnt) ? fb[(nft + fl) * NK + k2] : 0.0f;
            }
        }
        float a = 0.0f;
        if (lane < fcnt) {
            const float* wb = s_fbT[pb] + (h * 64) * FBT_STRIDE + lane;
            #pragma unroll
            for (int kk = 0; kk < 64; kk += 4) {
                float4 d4 = *reinterpret_cast<const float4*>(dr + kk);
                a = fmaf(d4.x, wb[(kk + 0) * FBT_STRIDE], a);
                a = fmaf(d4.y, wb[(kk + 1) * FBT_STRIDE], a);
                a = fmaf(d4.z, wb[(kk + 2) * FBT_STRIDE], a);
                a = fmaf(d4.w, wb[(kk + 3) * FBT_STRIDE], a);
            }
        }
        if (h == 1 && lane < fcnt) s_part[tile & 1][r][lane] = a;
        if (hp) {
            #pragma unroll
            for (int j = 0; j < 8; j++) {
                int i = tid + j * THREADS;
                int fl = i >> 7, k2 = i & (NK - 1);
                if (fl < nfcnt) s_fbT[1 - pb][k2 * FBT_STRIDE + fl] = pre[j];
            }
        }
        __syncthreads();
        if (h == 0 && lane < fcnt) {
            float tot = a + s_part[tile & 1][r][lane];   // fixed order h0+h1
            if (!done) {
                int f = ft + lane;
                size_t idx = (size_t)(row0 + r) * SPEC_STRIDE + f;
                float grad = (-2.0f * INV_N_C) * tot;
                float bn   = fmaf(MOM_C, g_buf[idx], grad);
                g_buf[idx] = bn;
                g_spec[idx] = fmaxf(fmaf(-LR_C, bn, g_spec[idx]), 0.0f);
            }
        }
        pb ^= 1;
    }

    // ---- Tail: last block reduces loss + latches stop flag ----
    __threadfence();
    __syncthreads();   // every thread's fence precedes the ticket below
    if (tid == 0) {
        int t = atomicAdd(&g_ticket, 1);
        s_last = (t == NBLOCKS - 1) ? 1 : 0;
    }
    __syncthreads();
    if (s_last) {
        float s = 0.0f;
        if (tid < 256) {
            #pragma unroll
            for (int j = 0; j < NROWS / 256; j++)
                s += __ldcg(&g_rowloss[tid + j * 256]);
            #pragma unroll
            for (int off = 16; off; off >>= 1)
                s += __shfl_xor_sync(0xffffffffu, s, off);
            if ((tid & 31) == 0) s_warp[tid >> 5] = s;
        }
        __syncthreads();
        if (tid == 0) {
            float tot = 0.0f;
            #pragma unroll
            for (int w = 0; w < 8; w++) tot += s_warp[w];
            float loss = tot * INV_N_C;
            if (!g_done) {
                float prev = g_prev_loss;
                int stop = (loss < TOL_LOSS_C) || (fabsf(prev - loss) < TOL_CHANGE_C);
                g_prev_loss = loss;
                if (stop) g_done = 1;
            }
            g_ticket = 0;   // re-arm for next launch
        }
    }
}

// ---------------------------------------------------------------------------
// out[b][f][t] = g_spec[(b*T + t)*SPEC_STRIDE + f]
__global__ void transpose_kernel(float* __restrict__ out) {
    __shared__ float tile[32][33];
    int b  = blockIdx.z;
    int f0 = blockIdx.x * 32;
    int t0 = blockIdx.y * 32;
    int tx = threadIdx.x, ty = threadIdx.y;   // 32 x 8
    for (int i = ty; i < 32; i += 8) {
        int f = f0 + tx, t = t0 + i;
        tile[i][tx] = (f < NF)
            ? g_spec[((size_t)(b * TT + t)) * SPEC_STRIDE + f] : 0.0f;
    }
    __syncthreads();
    for (int i = ty; i < 32; i += 8) {
        int f = f0 + i, t = t0 + tx;
        if (f < NF) out[((size_t)b * NF + f) * TT + t] = tile[tx][i];
    }
}

// ---------------------------------------------------------------------------
extern "C" void kernel_launch(void* const* d_in, const int* in_sizes, int n_in,
                              void* d_out, int out_size) {
    // Identify inputs by element count (robust to ordering)
    const float* barkspec  = nullptr;   // 4*128*512   = 262144
    const float* fb        = nullptr;   // 513*128     = 65664
    const float* spec_init = nullptr;   // 4*512*513   = 1050624
    for (int i = 0; i < n_in; i++) {
        if (in_sizes[i] == BB * NK * TT)      barkspec  = (const float*)d_in[i];
        else if (in_sizes[i] == NF * NK)      fb        = (const float*)d_in[i];
        else if (in_sizes[i] == NROWS * NF)   spec_init = (const float*)d_in[i];
    }
    float* out = (float*)d_out;

    init_kernel<<<(NROWS * NF + 255) / 256, 256>>>(spec_init);
    for (int it = 0; it < MAX_ITER_C; it++) {
        iter_kernel<<<NBLOCKS, THREADS>>>(barkspec, fb);
    }
    dim3 tgrid((NF + 31) / 32, TT / 32, BB);
    transpose_kernel<<<tgrid, dim3(32, 8)>>>(out);
}